// round 16
// baseline (speedup 1.0000x reference)
#include <cuda_runtime.h>
#include <stdint.h>

// Problem constants
#define NSAMP 1000000
#define KMIX  64
#define DDIM  16

// Opaque 1 — global load ptxas cannot constant-fold; mad.lo.u32 by this value
// stays IMAD (off the saturated ALU pipe).
__device__ uint32_t g_one = 1u;

// ---------------------------------------------------------------------------
// Threefry-2x32, key (0,42), partitionable counter (0,i), combine o0^o1.
// Input c42 = i + 42 (prefolded).
// Per round: x0 += x1 as IMAD (FMA pipe); rotl via mul.wide.u32 (IMAD.WIDE,
// FMA pipe: 64-bit x1<<r has halves {x1<<r, x1>>(32-r)}), then the combine
// (lo|hi)^x0 fuses to ONE LOP3 (ALU). Net: 2 ALU/round -> 1 ALU + 1 FMA.
// Keyschedule adds are immediate IMADs (off-ALU).
// ---------------------------------------------------------------------------
__device__ __forceinline__ uint32_t tf_bits(uint32_t c42, uint32_t one) {
    uint32_t x1 = c42;
    uint32_t x0 = x1;                       // round-1 specialized (x0 starts 0)
    x1 = __funnelshift_l(x1, x1, 13) ^ x0;

#define TFR(r) { \
    asm("mad.lo.u32 %0, %1, %2, %0;" : "+r"(x0) : "r"(x1), "r"(one)); \
    uint64_t w_; \
    asm("mul.wide.u32 %0, %1, %2;" : "=l"(w_) : "r"(x1), "r"(1u << (r))); \
    x1 = (((uint32_t)w_) | ((uint32_t)(w_ >> 32))) ^ x0; }
#define KADD(v, c) asm("mad.lo.u32 %0, %1, %2, %0;" : "+r"(v) : "r"(one), "n"(c))
    TFR(15) TFR(26) TFR(6)
    KADD(x0, 42);          KADD(x1, 0x1BD11BF1);   // ks2+1
    TFR(17) TFR(29) TFR(16) TFR(24)
    KADD(x0, 0x1BD11BF0);  KADD(x1, 2);            // ks2 ; ks0+2
    TFR(13) TFR(15) TFR(26) TFR(6)
    /* x0 += ks0 (=0): skip */ KADD(x1, 45);       // ks1+3
    TFR(17) TFR(29) TFR(16) TFR(24)
    KADD(x0, 42);          KADD(x1, 0x1BD11BF4);   // ks1 ; ks2+4
    TFR(13) TFR(15) TFR(26) TFR(6)
    KADD(x0, 0x1BD11BF0);  KADD(x1, 5);            // ks2 ; ks0+5
#undef TFR
#undef KADD
    return x0 ^ x1;
}

// ---------------------------------------------------------------------------
// Fused kernel (R14 champion structure): per-thread categorical sample, then
// warp-cooperative matvec (4 passes, 4 lanes/sample, z via shfl).
// Screen: argmin_k log2(u_k)*(-ln2/p_k); exact reference-formula rescan when
// top-2 margin < 4e-4 + 4e-4*m1 (3.3x worst-case MUFU.LG2 margin error).
// ---------------------------------------------------------------------------
__global__ __launch_bounds__(256) void fused_kernel(
    const float* __restrict__ pi,
    const float* __restrict__ x,
    const float* __restrict__ means,
    const float* __restrict__ Ls,
    float* __restrict__ y)
{
    __shared__ float s_w2n[KMIX];
    __shared__ float s_logit[KMIX];
    __shared__ float s_sum;

    // Block-local logits (serial sum order identical to verified runs).
    if (threadIdx.x == 0) {
        float s = 0.0f;
        for (int k = 0; k < KMIX; k++) s += pi[k];
        s_sum = s;
    }
    __syncthreads();
    if (threadIdx.x < KMIX) {
        float ssum = s_sum;
        s_logit[threadIdx.x] = logf(pi[threadIdx.x] / ssum);
        s_w2n[threadIdx.x]   = -0.6931471805599453f * (ssum / pi[threadIdx.x]);
    }
    __syncthreads();

    unsigned blockBase = blockIdx.x * 256u;
    unsigned warpBase  = blockBase + (threadIdx.x & ~31u);
    if (warpBase >= NSAMP) return;           // whole-warp guard (NSAMP % 32 == 0)

    unsigned n   = blockBase + threadIdx.x;  // this thread's sample (valid)
    int     lane = threadIdx.x & 31;

    uint32_t one = g_one;                    // opaque 1 (global load)
    uint32_t b42 = n * 64u + 42u;

    // ---- categorical sample (screen) ----
    const float INF = __int_as_float(0x7F800000);
    float m1 = INF, m2 = INF;
    int i1 = 0;

    #pragma unroll 8
    for (int k = 0; k < KMIX; k++) {
        uint32_t bits = tf_bits(b42 + (uint32_t)k, one);
        uint32_t fb;
        // fb = (bits >> 9) + 0x3F800000 in one IMAD.HI (off-ALU)
        asm("mad.hi.u32 %0, %1, %2, %3;"
            : "=r"(fb) : "r"(bits), "r"(0x00800000u), "r"(0x3F800000u));
        float u = __uint_as_float(fb) - 1.0f;           // [0,1)
        float m = __log2f(u) * s_w2n[k];                // >=0 (u=0 -> +inf, never min)
        if (m < m1) { m2 = m1; m1 = m; i1 = k; }
        else        { m2 = fminf(m2, m); }
    }

    int z = i1;
    if (m2 - m1 < 4e-4f + 4e-4f * m1) {
        // Exact reference-formula rescan (verified bit-exact path).
        float best = -INF;
        int zi = 0;
        for (int k = 0; k < KMIX; k++) {
            uint32_t bits = tf_bits(b42 + (uint32_t)k, one);
            float f  = __uint_as_float(0x3F800000u | (bits >> 9)) - 1.0f;
            float uu = fmaxf(f, 1.17549435e-38f);
            float v  = -logf(-logf(uu)) + s_logit[k];
            if (v > best) { best = v; zi = k; }
        }
        z = zi;
    }

    // ---- warp-cooperative matvec: 4 passes, 4 lanes per sample ----
    int q = lane & 3;                        // output quarter (e = 4q..4q+3)

    #pragma unroll 1
    for (int pass = 0; pass < 4; pass++) {
        int src = pass * 8 + (lane >> 2);    // lane that sampled this pass's z
        int zz  = __shfl_sync(0xFFFFFFFFu, z, src);
        unsigned ns = warpBase + (unsigned)src;

        // x[ns]: 4 lanes per group load same addresses (L1 broadcast)
        const float4* xg = (const float4*)x + ns * 4;
        float4 xa = __ldg(xg + 0);
        float4 xb = __ldg(xg + 1);
        float4 xc = __ldg(xg + 2);
        float4 xd = __ldg(xg + 3);
        float xr[16] = { xa.x, xa.y, xa.z, xa.w,
                         xb.x, xb.y, xb.z, xb.w,
                         xc.x, xc.y, xc.z, xc.w,
                         xd.x, xd.y, xd.z, xd.w };

        const float4* L4 = (const float4*)Ls + zz * 64 + q;   // row d -> L4[d*4]
        float4 acc = __ldg((const float4*)means + zz * 4 + q);

        #pragma unroll
        for (int d = 0; d < DDIM; d++) {
            float4 lv = __ldg(L4 + d * 4);
            float xs = xr[d];
            acc.x = fmaf(xs, lv.x, acc.x);
            acc.y = fmaf(xs, lv.y, acc.y);
            acc.z = fmaf(xs, lv.z, acc.z);
            acc.w = fmaf(xs, lv.w, acc.w);
        }

        ((float4*)y)[ns * 4 + q] = acc;      // 512B contiguous per warp
    }
}

// ---------------------------------------------------------------------------
extern "C" void kernel_launch(void* const* d_in, const int* in_sizes, int n_in,
                              void* d_out, int out_size) {
    const float* x     = (const float*)d_in[0];   // (N, D)
    const float* pi    = (const float*)d_in[1];   // (K,)
    const float* means = (const float*)d_in[2];   // (K, D)
    const float* Ls    = (const float*)d_in[3];   // (K, D, D)
    float* y           = (float*)d_out;           // (N, D)

    fused_kernel<<<(NSAMP + 255) / 256, 256>>>(pi, x, means, Ls, y);
}